// round 9
// baseline (speedup 1.0000x reference)
#include <cuda_runtime.h>
#include <cuda_fp16.h>
#include <cstdint>
#include <math.h>

#define SN       150000
#define DIM      512
#define NB       100
#define NUSE     104                 // computed n columns (13 tiles of 8)
#define NTILES   13
#define TALF     0.07f
#define S_PER_CTA 512
#define NCTA     ((SN + S_PER_CTA - 1) / S_PER_CTA)   // 293
#define NCTA_A   (NCTA / 2)                           // 146

// B words: 32 ksteps x 104 n x 8 words (f16x2, fragment-packed)
#define BW        (32 * NUSE * 8)                     // 26624 words = 104 KB
#define AST_BYTES (16 * 2 * 1024)                     // 16 warps x 2 x 1KB staging
#define SMEM_MAIN (BW * 4 + AST_BYTES + 16 * NUSE * 4 + 16 * 32 * 4)

// Static device scratch (no allocations allowed)
__device__ __align__(1024) unsigned g_B[BW];
__device__ float g_Psum[NCTA * 128];
__device__ float g_pos[128];
__device__ float g_logZ[128];

// ---------------------------------------------------------------------------
__device__ __forceinline__ unsigned pack_f16x2(float lo, float hi) {
    unsigned r;  // first source -> high half
    asm("cvt.rn.f16x2.f32 %0, %1, %2;" : "=r"(r) : "f"(hi), "f"(lo));
    return r;
}
__device__ __forceinline__ void mma_f16acc(unsigned c[2], const unsigned* a,
                                           unsigned b0, unsigned b1) {
    asm volatile(
        "mma.sync.aligned.m16n8k16.row.col.f16.f16.f16.f16 "
        "{%0,%1},{%2,%3,%4,%5},{%6,%7},{%0,%1};\n"
        : "+r"(c[0]), "+r"(c[1])
        : "r"(a[0]), "r"(a[1]), "r"(a[2]), "r"(a[3]), "r"(b0), "r"(b1));
}
__device__ __forceinline__ void cp_async16(void* smem_dst, const void* gsrc) {
    unsigned s = (unsigned)__cvta_generic_to_shared(smem_dst);
    asm volatile("cp.async.cg.shared.global [%0], [%1], 16;\n" :: "r"(s), "l"(gsrc));
}
__device__ __forceinline__ unsigned smem_u32(const void* p) {
    return (unsigned)__cvta_generic_to_shared(p);
}

// ---------------------------------------------------------------------------
// prep: B'[n][k] = f16( fea[n][k] / (TAL*||fea[n]||) ), fragment layout:
//   word[(kstep*104 + n)*8 + c], kstep=k/16, c=2*tig+h -> k0 = kstep*16+h*8+2*tig
// ---------------------------------------------------------------------------
__global__ void prep_kernel(const float* __restrict__ fea) {
    int n = blockIdx.x;   // 0..103
    int t = threadIdx.x;  // 128
    __shared__ float red[128];
    __shared__ float row[512];
    float v[4]; float ss = 0.f;
    if (n < NB) {
#pragma unroll
        for (int i = 0; i < 4; i++) { v[i] = fea[n * DIM + t + i * 128]; ss += v[i] * v[i]; }
    } else { v[0] = v[1] = v[2] = v[3] = 0.f; }
    red[t] = ss; __syncthreads();
    for (int off = 64; off > 0; off >>= 1) { if (t < off) red[t] += red[t + off]; __syncthreads(); }
    float scale = (n < NB) ? (rsqrtf(red[0]) / TALF) : 0.f;
#pragma unroll
    for (int i = 0; i < 4; i++) row[t + i * 128] = v[i] * scale;
    __syncthreads();
#pragma unroll
    for (int i = 0; i < 2; i++) {
        int w = t + i * 128;
        int kstep = w >> 3;
        int c = w & 7;
        int k0 = kstep * 16 + (c & 1) * 8 + (c >> 1) * 2;
        g_B[(kstep * NUSE + n) * 8 + c] = pack_f16x2(row[k0], row[k0 + 1]);
    }
}

// ---------------------------------------------------------------------------
// pos: ex[label[n], n] exact fp32; label dtype sniffed (int64 vs int32)
// ---------------------------------------------------------------------------
__global__ void pos_kernel(const float* __restrict__ att,
                           const float* __restrict__ fea,
                           const int* __restrict__ label_raw) {
    int n = blockIdx.x, t = threadIdx.x;
    bool is64 = (label_raw[1] == 0) && (label_raw[3] == 0) &&
                (label_raw[5] == 0) && (label_raw[7] == 0);
    int lab = is64 ? (int)(((const long long*)label_raw)[n]) : label_raw[n];
    if (lab < 0) lab = 0;
    if (lab >= SN) lab = SN - 1;
    float dot = 0.f, asq = 0.f, fsq = 0.f;
    for (int d = t; d < DIM; d += 128) {
        float a = att[(size_t)d * SN + (size_t)lab];
        float f = fea[n * DIM + d];
        dot += a * f; asq += a * a; fsq += f * f;
    }
    __shared__ float r1[128], r2[128], r3[128];
    r1[t] = dot; r2[t] = asq; r3[t] = fsq; __syncthreads();
    for (int off = 64; off > 0; off >>= 1) {
        if (t < off) { r1[t] += r1[t+off]; r2[t] += r2[t+off]; r3[t] += r3[t+off]; }
        __syncthreads();
    }
    if (t == 0) g_pos[n] = r1[0] / (TALF * sqrtf(r2[0]) * sqrtf(r3[0]));
}

// ---------------------------------------------------------------------------
// main: 293 CTAs (2 launches) x 512 threads. Tile 512 s x 104 n, K=512.
//   Warp owns 32 s x all 13 n-tiles. A: coalesced LDG.128 -> f16 smem staging
//   (swizzled, per-warp double buffer) -> ldmatrix.x4.trans fragments.
//   B resident in smem. Norms exact fp32 from the same float4 loads.
// ---------------------------------------------------------------------------
#define LOADG(q)                                                            \
    do {                                                                    \
        const float* ap_ = att + (size_t)((q) * 16 + g8) * SN_ + s0;        \
        _Pragma("unroll")                                                   \
        for (int i_ = 0; i_ < 4; i_++) {                                    \
            const float* p_ = ap_ + (size_t)(4 * i_) * SN_;                 \
            if (v4) G[i_] = *(const float4*)p_;                             \
            else {                                                          \
                G[i_].x = vs0 ? p_[0] : 0.f;                                \
                G[i_].y = vs1 ? p_[1] : 0.f;                                \
                G[i_].z = vs2 ? p_[2] : 0.f;                                \
                G[i_].w = vs3 ? p_[3] : 0.f;                                \
            }                                                               \
        }                                                                   \
    } while (0)

#define STSG(buf)                                                           \
    do {                                                                    \
        _Pragma("unroll")                                                   \
        for (int i_ = 0; i_ < 4; i_++) {                                    \
            sq4[0] += G[i_].x * G[i_].x;                                    \
            sq4[1] += G[i_].y * G[i_].y;                                    \
            sq4[2] += G[i_].z * G[i_].z;                                    \
            sq4[3] += G[i_].w * G[i_].w;                                    \
            int kl_ = i_ * 4 + g8;                                          \
            unsigned off_ = (unsigned)(kl_ * 64 +                           \
                ((cch ^ ((kl_ >> 1) & 3)) * 16) + hh * 8);                  \
            *(uint2*)(Awarp + (buf) * 1024 + off_) =                        \
                make_uint2(pack_f16x2(G[i_].x, G[i_].y),                    \
                           pack_f16x2(G[i_].z, G[i_].w));                   \
        }                                                                   \
    } while (0)

#define LDSM(buf, F)                                                        \
    do {                                                                    \
        unsigned base_ = Abase + (buf) * 1024 + mrow * 64;                  \
        unsigned ad0_ = base_ + (unsigned)(((codd) ^ msw) * 16);            \
        unsigned ad1_ = base_ + (unsigned)(((2 + codd) ^ msw) * 16);        \
        asm volatile(                                                       \
            "ldmatrix.sync.aligned.m8n8.x4.trans.shared.b16 "               \
            "{%0,%1,%2,%3}, [%4];"                                          \
            : "=r"((F)[0]), "=r"((F)[1]), "=r"((F)[2]), "=r"((F)[3])        \
            : "r"(ad0_));                                                   \
        asm volatile(                                                       \
            "ldmatrix.sync.aligned.m8n8.x4.trans.shared.b16 "               \
            "{%0,%1,%2,%3}, [%4];"                                          \
            : "=r"((F)[4]), "=r"((F)[5]), "=r"((F)[6]), "=r"((F)[7])        \
            : "r"(ad1_));                                                   \
    } while (0)

#define COMPUTE(q, F)                                                       \
    do {                                                                    \
        const uint2* bq_ = (const uint2*)Bsm + (q) * (NUSE * 4) + tig;      \
        _Pragma("unroll")                                                   \
        for (int nt_ = 0; nt_ < NTILES; nt_++) {                            \
            uint2 b_ = bq_[(nt_ * 8 + gid) * 4];                            \
            mma_f16acc(acc[0][nt_], (F) + 0, b_.x, b_.y);                   \
            mma_f16acc(acc[1][nt_], (F) + 4, b_.x, b_.y);                   \
        }                                                                   \
    } while (0)

__global__ void __launch_bounds__(512, 1)
main_kernel(const float* __restrict__ att, int cta_base) {
    extern __shared__ __align__(128) unsigned char smraw[];
    unsigned*      Bsm    = (unsigned*)smraw;                        // BW words
    unsigned char* Ast    = smraw + BW * 4;                          // staging
    float*         colacc = (float*)(smraw + BW * 4 + AST_BYTES);    // 16 x NUSE
    float*         nrm    = colacc + 16 * NUSE;                      // 16 x 32

    const int tid   = threadIdx.x;
    const int lane  = tid & 31;
    const int warp  = tid >> 5;
    const int gid   = lane >> 2;
    const int tig   = lane & 3;
    const int cta   = cta_base + blockIdx.x;
    const int s_w   = cta * S_PER_CTA + warp * 32;
    const size_t SN_ = (size_t)SN;

    // A-load geometry: thread covers k-rows {q*16 + 4i + g8}, s = s0..s0+3
    const int g8 = lane >> 3;              // 0..3
    const int sb = (lane & 7) * 4;         // 0..28
    const int s0 = s_w + sb;
    const bool v4  = (s0 + 3) < SN;
    const bool vs0 = (s0 + 0) < SN, vs1 = (s0 + 1) < SN;
    const bool vs2 = (s0 + 2) < SN, vs3 = (s0 + 3) < SN;
    const int cch = (lane & 7) >> 1;       // 16B chunk within k-row
    const int hh  = lane & 1;              // 8B half within chunk

    // ldmatrix geometry
    const int mrow = (((lane >> 4) & 1) << 3) + (lane & 7);  // k-row 0..15
    const int codd = (lane >> 3) & 1;                        // matrix parity
    const int msw  = (mrow >> 1) & 3;                        // bank swizzle

    unsigned char* Awarp = Ast + warp * 2048;
    const unsigned Abase = smem_u32(Awarp);

    int  srow[4];
    bool pv[4];
#pragma unroll
    for (int j = 0; j < 4; j++) {
        srow[j] = s_w + 8 * j + gid;
        pv[j]   = (srow[j] < SN);
    }

    unsigned acc[2][NTILES][2];
#pragma unroll
    for (int a = 0; a < 2; a++)
#pragma unroll
        for (int b = 0; b < NTILES; b++) { acc[a][b][0] = 0u; acc[a][b][1] = 0u; }
    float sq4[4] = {0.f, 0.f, 0.f, 0.f};

    // one-shot B fill: 26624 words = 6656 x 16B, 13 per thread
#pragma unroll
    for (int i = 0; i < 13; i++) {
        int w = (tid + i * 512) * 4;
        cp_async16(&Bsm[w], &g_B[w]);
    }
    asm volatile("cp.async.commit_group;\n");

    float4 G[4];
    unsigned F[2][8];

    LOADG(0);
    asm volatile("cp.async.wait_group 0;\n");
    __syncthreads();   // the ONLY CTA barrier before the epilogue

    STSG(0);
    __syncwarp();
    LDSM(0, F[0]);

#pragma unroll 2
    for (int q = 0; q < 32; q++) {
        if (q < 31) LOADG(q + 1);
        COMPUTE(q, F[q & 1]);
        if (q < 31) {
            STSG((q + 1) & 1);
            __syncwarp();
            LDSM((q + 1) & 1, F[(q + 1) & 1]);
        }
    }

    // norms: sum the 4 k-residue partials (lanes l, l+8, l+16, l+24)
#pragma unroll
    for (int j = 0; j < 4; j++) {
        sq4[j] += __shfl_down_sync(0xffffffffu, sq4[j], 16);
        sq4[j] += __shfl_down_sync(0xffffffffu, sq4[j], 8);
    }
    if (lane < 8) {
#pragma unroll
        for (int j = 0; j < 4; j++)
            nrm[warp * 32 + lane * 4 + j] = sq4[j];
    }
    __syncwarp();
    float inv[4];
#pragma unroll
    for (int j = 0; j < 4; j++)
        inv[j] = rsqrtf(nrm[warp * 32 + gid + 8 * j]);

    // epilogue: unpack f16 accum, scale, exp, warp-level column sums
#pragma unroll
    for (int nt = 0; nt < NTILES; ++nt) {
        float e0 = 0.f, e1 = 0.f;
#pragma unroll
        for (int mf = 0; mf < 2; ++mf) {
            int j0 = 2 * mf, j1 = 2 * mf + 1;
            float2 v0 = __half22float2(*reinterpret_cast<__half2*>(&acc[mf][nt][0]));
            float2 v1 = __half22float2(*reinterpret_cast<__half2*>(&acc[mf][nt][1]));
            if (pv[j0]) {
                e0 += __expf(v0.x * inv[j0]);
                e1 += __expf(v0.y * inv[j0]);
            }
            if (pv[j1]) {
                e0 += __expf(v1.x * inv[j1]);
                e1 += __expf(v1.y * inv[j1]);
            }
        }
        e0 += __shfl_down_sync(0xffffffffu, e0, 16);
        e1 += __shfl_down_sync(0xffffffffu, e1, 16);
        e0 += __shfl_down_sync(0xffffffffu, e0, 8);
        e1 += __shfl_down_sync(0xffffffffu, e1, 8);
        e0 += __shfl_down_sync(0xffffffffu, e0, 4);
        e1 += __shfl_down_sync(0xffffffffu, e1, 4);
        if (gid == 0) {
            colacc[warp * NUSE + nt * 8 + 2 * tig]     = e0;
            colacc[warp * NUSE + nt * 8 + 2 * tig + 1] = e1;
        }
    }
    __syncthreads();

    if (tid < NUSE) {
        float t = 0.f;
#pragma unroll
        for (int g = 0; g < 16; ++g) t += colacc[g * NUSE + tid];
        g_Psum[cta * 128 + tid] = t;
    }
}

// ---------------------------------------------------------------------------
__global__ void reduce_kernel() {
    int n = blockIdx.x;    // 0..NUSE-1
    int t = threadIdx.x;   // 256
    __shared__ float red[256];
    float sum = 0.f;
    for (int c = t; c < NCTA; c += 256) sum += g_Psum[c * 128 + n];
    red[t] = sum; __syncthreads();
    for (int off = 128; off > 0; off >>= 1) { if (t < off) red[t] += red[t + off]; __syncthreads(); }
    if (t == 0) g_logZ[n] = logf(red[0]);
}

__global__ void final_kernel(float* __restrict__ out) {
    int t = threadIdx.x;   // 128
    __shared__ float red[128];
    float v = (t < NB) ? (g_logZ[t] - g_pos[t]) : 0.f;
    red[t] = v; __syncthreads();
    for (int off = 64; off > 0; off >>= 1) { if (t < off) red[t] += red[t + off]; __syncthreads(); }
    if (t == 0) out[0] = red[0] / (float)NB;
}

// ---------------------------------------------------------------------------
extern "C" void kernel_launch(void* const* d_in, const int* in_sizes, int n_in,
                              void* d_out, int out_size) {
    int ia = 0, ifea = 1, ilab = 2;
    for (int i = 0; i < n_in; i++) {
        if (in_sizes[i] > 10000000) ia = i;
        else if (in_sizes[i] > 100000) ifea = i;
        else ilab = i;
    }
    const float* att   = (const float*)d_in[ia];
    const float* fea   = (const float*)d_in[ifea];
    const int*   label = (const int*)d_in[ilab];
    float* out = (float*)d_out;

    // Idempotent; safe under graph capture (no allocation, no sync).
    cudaFuncSetAttribute(main_kernel, cudaFuncAttributeMaxDynamicSharedMemorySize,
                         SMEM_MAIN);

    prep_kernel<<<NUSE, 128>>>(fea);
    pos_kernel<<<NB, 128>>>(att, fea, label);
    main_kernel<<<NCTA_A, 512, SMEM_MAIN>>>(att, 0);
    main_kernel<<<NCTA - NCTA_A, 512, SMEM_MAIN>>>(att, NCTA_A);
    reduce_kernel<<<NUSE, 256>>>();
    final_kernel<<<1, 128>>>(out);
}

// round 10
// speedup vs baseline: 1.0058x; 1.0058x over previous
#include <cuda_runtime.h>
#include <cuda_fp16.h>
#include <cstdint>
#include <math.h>

#define SN       150000
#define DIM      512
#define NB       100
#define NUSE     104                 // computed n columns (13 tiles of 8)
#define NTILES   13
#define TALF     0.07f
#define S_PER_CTA 512
#define NCTA     ((SN + S_PER_CTA - 1) / S_PER_CTA)   // 293
#define NCTA_A   (NCTA / 2)                           // 146

// B words: 32 ksteps x 104 n x 8 words (f16x2, fragment-packed)
#define BW        (32 * NUSE * 8)                     // 26624 words = 104 KB
#define AST_BYTES (16 * 3 * 1024)                     // 16 warps x 3 x 1KB staging
#define SMEM_MAIN (BW * 4 + AST_BYTES + 16 * NUSE * 4 + 16 * 32 * 4)

// Static device scratch (no allocations allowed)
__device__ __align__(1024) unsigned g_B[BW];
__device__ float g_Psum[NCTA * 128];
__device__ float g_pos[128];
__device__ float g_logZ[128];

// ---------------------------------------------------------------------------
__device__ __forceinline__ unsigned pack_f16x2(float lo, float hi) {
    unsigned r;  // first source -> high half
    asm("cvt.rn.f16x2.f32 %0, %1, %2;" : "=r"(r) : "f"(hi), "f"(lo));
    return r;
}
__device__ __forceinline__ void mma_f16acc(unsigned c[2], const unsigned* a,
                                           unsigned b0, unsigned b1) {
    asm volatile(
        "mma.sync.aligned.m16n8k16.row.col.f16.f16.f16.f16 "
        "{%0,%1},{%2,%3,%4,%5},{%6,%7},{%0,%1};\n"
        : "+r"(c[0]), "+r"(c[1])
        : "r"(a[0]), "r"(a[1]), "r"(a[2]), "r"(a[3]), "r"(b0), "r"(b1));
}
__device__ __forceinline__ void cp_async16(void* smem_dst, const void* gsrc) {
    unsigned s = (unsigned)__cvta_generic_to_shared(smem_dst);
    asm volatile("cp.async.cg.shared.global [%0], [%1], 16;\n" :: "r"(s), "l"(gsrc));
}
__device__ __forceinline__ unsigned smem_u32(const void* p) {
    return (unsigned)__cvta_generic_to_shared(p);
}

// ---------------------------------------------------------------------------
// prep: B'[n][k] = f16( fea[n][k] / (TAL*||fea[n]||) ), fragment layout:
//   word[(kstep*104 + n)*8 + c], kstep=k/16, c=2*tig+h -> k0 = kstep*16+h*8+2*tig
// ---------------------------------------------------------------------------
__global__ void prep_kernel(const float* __restrict__ fea) {
    int n = blockIdx.x;   // 0..103
    int t = threadIdx.x;  // 128
    __shared__ float red[128];
    __shared__ float row[512];
    float v[4]; float ss = 0.f;
    if (n < NB) {
#pragma unroll
        for (int i = 0; i < 4; i++) { v[i] = fea[n * DIM + t + i * 128]; ss += v[i] * v[i]; }
    } else { v[0] = v[1] = v[2] = v[3] = 0.f; }
    red[t] = ss; __syncthreads();
    for (int off = 64; off > 0; off >>= 1) { if (t < off) red[t] += red[t + off]; __syncthreads(); }
    float scale = (n < NB) ? (rsqrtf(red[0]) / TALF) : 0.f;
#pragma unroll
    for (int i = 0; i < 4; i++) row[t + i * 128] = v[i] * scale;
    __syncthreads();
#pragma unroll
    for (int i = 0; i < 2; i++) {
        int w = t + i * 128;
        int kstep = w >> 3;
        int c = w & 7;
        int k0 = kstep * 16 + (c & 1) * 8 + (c >> 1) * 2;
        g_B[(kstep * NUSE + n) * 8 + c] = pack_f16x2(row[k0], row[k0 + 1]);
    }
}

// ---------------------------------------------------------------------------
// pos: ex[label[n], n] exact fp32; label dtype sniffed (int64 vs int32)
// ---------------------------------------------------------------------------
__global__ void pos_kernel(const float* __restrict__ att,
                           const float* __restrict__ fea,
                           const int* __restrict__ label_raw) {
    int n = blockIdx.x, t = threadIdx.x;
    bool is64 = (label_raw[1] == 0) && (label_raw[3] == 0) &&
                (label_raw[5] == 0) && (label_raw[7] == 0);
    int lab = is64 ? (int)(((const long long*)label_raw)[n]) : label_raw[n];
    if (lab < 0) lab = 0;
    if (lab >= SN) lab = SN - 1;
    float dot = 0.f, asq = 0.f, fsq = 0.f;
    for (int d = t; d < DIM; d += 128) {
        float a = att[(size_t)d * SN + (size_t)lab];
        float f = fea[n * DIM + d];
        dot += a * f; asq += a * a; fsq += f * f;
    }
    __shared__ float r1[128], r2[128], r3[128];
    r1[t] = dot; r2[t] = asq; r3[t] = fsq; __syncthreads();
    for (int off = 64; off > 0; off >>= 1) {
        if (t < off) { r1[t] += r1[t+off]; r2[t] += r2[t+off]; r3[t] += r3[t+off]; }
        __syncthreads();
    }
    if (t == 0) g_pos[n] = r1[0] / (TALF * sqrtf(r2[0]) * sqrtf(r3[0]));
}

// ---------------------------------------------------------------------------
// main: 293 CTAs (2 launches) x 512 threads. Tile 512 s x 104 n, K=512.
//   Warp owns 32 s x all 13 n-tiles. A: coalesced LDG.128 -> f16 smem staging
//   (swizzled, per-warp TRIPLE buffer) -> ldmatrix.x4.trans fragments, with
//   every producer->consumer edge spanning one full COMPUTE (latency hidden).
//   B resident in smem. Norms exact fp32 from the same float4 loads.
// ---------------------------------------------------------------------------
#define LOADG(q)                                                            \
    do {                                                                    \
        const float* ap_ = att + (size_t)((q) * 16 + g8) * SN_ + s0;        \
        _Pragma("unroll")                                                   \
        for (int i_ = 0; i_ < 4; i_++) {                                    \
            const float* p_ = ap_ + (size_t)(4 * i_) * SN_;                 \
            if (v4) G[i_] = *(const float4*)p_;                             \
            else {                                                          \
                G[i_].x = vs0 ? p_[0] : 0.f;                                \
                G[i_].y = vs1 ? p_[1] : 0.f;                                \
                G[i_].z = vs2 ? p_[2] : 0.f;                                \
                G[i_].w = vs3 ? p_[3] : 0.f;                                \
            }                                                               \
        }                                                                   \
    } while (0)

#define STSG(buf)                                                           \
    do {                                                                    \
        _Pragma("unroll")                                                   \
        for (int i_ = 0; i_ < 4; i_++) {                                    \
            sq4[0] += G[i_].x * G[i_].x;                                    \
            sq4[1] += G[i_].y * G[i_].y;                                    \
            sq4[2] += G[i_].z * G[i_].z;                                    \
            sq4[3] += G[i_].w * G[i_].w;                                    \
            int kl_ = i_ * 4 + g8;                                          \
            unsigned off_ = (unsigned)(kl_ * 64 +                           \
                ((cch ^ ((kl_ >> 1) & 3)) * 16) + hh * 8);                  \
            *(uint2*)(Awarp + (buf) * 1024 + off_) =                        \
                make_uint2(pack_f16x2(G[i_].x, G[i_].y),                    \
                           pack_f16x2(G[i_].z, G[i_].w));                   \
        }                                                                   \
    } while (0)

#define LDSM(buf, F)                                                        \
    do {                                                                    \
        unsigned base_ = Abase + (buf) * 1024 + mrow * 64;                  \
        unsigned ad0_ = base_ + (unsigned)(((codd) ^ msw) * 16);            \
        unsigned ad1_ = base_ + (unsigned)(((2 + codd) ^ msw) * 16);        \
        asm volatile(                                                       \
            "ldmatrix.sync.aligned.m8n8.x4.trans.shared.b16 "               \
            "{%0,%1,%2,%3}, [%4];"                                          \
            : "=r"((F)[0]), "=r"((F)[1]), "=r"((F)[2]), "=r"((F)[3])        \
            : "r"(ad0_));                                                   \
        asm volatile(                                                       \
            "ldmatrix.sync.aligned.m8n8.x4.trans.shared.b16 "               \
            "{%0,%1,%2,%3}, [%4];"                                          \
            : "=r"((F)[4]), "=r"((F)[5]), "=r"((F)[6]), "=r"((F)[7])        \
            : "r"(ad1_));                                                   \
    } while (0)

#define COMPUTE(q, F)                                                       \
    do {                                                                    \
        const uint2* bq_ = (const uint2*)Bsm + (q) * (NUSE * 4) + tig;      \
        _Pragma("unroll")                                                   \
        for (int nt_ = 0; nt_ < NTILES; nt_++) {                            \
            uint2 b_ = bq_[(nt_ * 8 + gid) * 4];                            \
            mma_f16acc(acc[0][nt_], (F) + 0, b_.x, b_.y);                   \
            mma_f16acc(acc[1][nt_], (F) + 4, b_.x, b_.y);                   \
        }                                                                   \
    } while (0)

__global__ void __launch_bounds__(512, 1)
main_kernel(const float* __restrict__ att, int cta_base) {
    extern __shared__ __align__(128) unsigned char smraw[];
    unsigned*      Bsm    = (unsigned*)smraw;                        // BW words
    unsigned char* Ast    = smraw + BW * 4;                          // staging
    float*         colacc = (float*)(smraw + BW * 4 + AST_BYTES);    // 16 x NUSE
    float*         nrm    = colacc + 16 * NUSE;                      // 16 x 32

    const int tid   = threadIdx.x;
    const int lane  = tid & 31;
    const int warp  = tid >> 5;
    const int gid   = lane >> 2;
    const int tig   = lane & 3;
    const int cta   = cta_base + blockIdx.x;
    const int s_w   = cta * S_PER_CTA + warp * 32;
    const size_t SN_ = (size_t)SN;

    // A-load geometry: thread covers k-rows {q*16 + 4i + g8}, s = s0..s0+3
    const int g8 = lane >> 3;              // 0..3
    const int sb = (lane & 7) * 4;         // 0..28
    const int s0 = s_w + sb;
    const bool v4  = (s0 + 3) < SN;
    const bool vs0 = (s0 + 0) < SN, vs1 = (s0 + 1) < SN;
    const bool vs2 = (s0 + 2) < SN, vs3 = (s0 + 3) < SN;
    const int cch = (lane & 7) >> 1;       // 16B chunk within k-row
    const int hh  = lane & 1;              // 8B half within chunk

    // ldmatrix geometry
    const int mrow = (((lane >> 4) & 1) << 3) + (lane & 7);  // k-row 0..15
    const int codd = (lane >> 3) & 1;                        // matrix parity
    const int msw  = (mrow >> 1) & 3;                        // bank swizzle

    unsigned char* Awarp = Ast + warp * 3072;
    const unsigned Abase = smem_u32(Awarp);

    int  srow[4];
    bool pv[4];
#pragma unroll
    for (int j = 0; j < 4; j++) {
        srow[j] = s_w + 8 * j + gid;
        pv[j]   = (srow[j] < SN);
    }

    unsigned acc[2][NTILES][2];
#pragma unroll
    for (int a = 0; a < 2; a++)
#pragma unroll
        for (int b = 0; b < NTILES; b++) { acc[a][b][0] = 0u; acc[a][b][1] = 0u; }
    float sq4[4] = {0.f, 0.f, 0.f, 0.f};

    // one-shot B fill: 26624 words = 6656 x 16B, 13 per thread
#pragma unroll
    for (int i = 0; i < 13; i++) {
        int w = (tid + i * 512) * 4;
        cp_async16(&Bsm[w], &g_B[w]);
    }
    asm volatile("cp.async.commit_group;\n");

    float4 G[4];
    unsigned F[2][8];

    // prologue: fill staging buffers 0 and 1, prime F[0]
    LOADG(0);
    asm volatile("cp.async.wait_group 0;\n");
    __syncthreads();   // the ONLY CTA barrier before the epilogue
    STSG(0);
    __syncwarp();
    LOADG(1);
    STSG(1);
    __syncwarp();
    LDSM(0, F[0]);

    // steady state, every dependency edge spans one COMPUTE:
    //   iter q: LDSM(q+1) [buf filled @ iter q-1]; LOADG(q+2);
    //           COMPUTE(q); STSG(q+2) [LDG covered by COMPUTE]; syncwarp
#pragma unroll 3
    for (int q = 0; q < 32; q++) {
        if (q + 1 < 32) LDSM((q + 1) % 3, F[(q + 1) & 1]);
        if (q + 2 < 32) LOADG(q + 2);
        COMPUTE(q, F[q & 1]);
        if (q + 2 < 32) {
            STSG((q + 2) % 3);
            __syncwarp();
        }
    }

    // norms: sum the 4 k-residue partials (lanes l, l+8, l+16, l+24)
#pragma unroll
    for (int j = 0; j < 4; j++) {
        sq4[j] += __shfl_down_sync(0xffffffffu, sq4[j], 16);
        sq4[j] += __shfl_down_sync(0xffffffffu, sq4[j], 8);
    }
    if (lane < 8) {
#pragma unroll
        for (int j = 0; j < 4; j++)
            nrm[warp * 32 + lane * 4 + j] = sq4[j];
    }
    __syncwarp();
    float inv[4];
#pragma unroll
    for (int j = 0; j < 4; j++)
        inv[j] = rsqrtf(nrm[warp * 32 + gid + 8 * j]);

    // epilogue: unpack f16 accum, scale, exp, warp-level column sums
#pragma unroll
    for (int nt = 0; nt < NTILES; ++nt) {
        float e0 = 0.f, e1 = 0.f;
#pragma unroll
        for (int mf = 0; mf < 2; ++mf) {
            int j0 = 2 * mf, j1 = 2 * mf + 1;
            float2 v0 = __half22float2(*reinterpret_cast<__half2*>(&acc[mf][nt][0]));
            float2 v1 = __half22float2(*reinterpret_cast<__half2*>(&acc[mf][nt][1]));
            if (pv[j0]) {
                e0 += __expf(v0.x * inv[j0]);
                e1 += __expf(v0.y * inv[j0]);
            }
            if (pv[j1]) {
                e0 += __expf(v1.x * inv[j1]);
                e1 += __expf(v1.y * inv[j1]);
            }
        }
        e0 += __shfl_down_sync(0xffffffffu, e0, 16);
        e1 += __shfl_down_sync(0xffffffffu, e1, 16);
        e0 += __shfl_down_sync(0xffffffffu, e0, 8);
        e1 += __shfl_down_sync(0xffffffffu, e1, 8);
        e0 += __shfl_down_sync(0xffffffffu, e0, 4);
        e1 += __shfl_down_sync(0xffffffffu, e1, 4);
        if (gid == 0) {
            colacc[warp * NUSE + nt * 8 + 2 * tig]     = e0;
            colacc[warp * NUSE + nt * 8 + 2 * tig + 1] = e1;
        }
    }
    __syncthreads();

    if (tid < NUSE) {
        float t = 0.f;
#pragma unroll
        for (int g = 0; g < 16; ++g) t += colacc[g * NUSE + tid];
        g_Psum[cta * 128 + tid] = t;
    }
}

// ---------------------------------------------------------------------------
__global__ void reduce_kernel() {
    int n = blockIdx.x;    // 0..NUSE-1
    int t = threadIdx.x;   // 256
    __shared__ float red[256];
    float sum = 0.f;
    for (int c = t; c < NCTA; c += 256) sum += g_Psum[c * 128 + n];
    red[t] = sum; __syncthreads();
    for (int off = 128; off > 0; off >>= 1) { if (t < off) red[t] += red[t + off]; __syncthreads(); }
    if (t == 0) g_logZ[n] = logf(red[0]);
}

__global__ void final_kernel(float* __restrict__ out) {
    int t = threadIdx.x;   // 128
    __shared__ float red[128];
    float v = (t < NB) ? (g_logZ[t] - g_pos[t]) : 0.f;
    red[t] = v; __syncthreads();
    for (int off = 64; off > 0; off >>= 1) { if (t < off) red[t] += red[t + off]; __syncthreads(); }
    if (t == 0) out[0] = red[0] / (float)NB;
}

// ---------------------------------------------------------------------------
extern "C" void kernel_launch(void* const* d_in, const int* in_sizes, int n_in,
                              void* d_out, int out_size) {
    int ia = 0, ifea = 1, ilab = 2;
    for (int i = 0; i < n_in; i++) {
        if (in_sizes[i] > 10000000) ia = i;
        else if (in_sizes[i] > 100000) ifea = i;
        else ilab = i;
    }
    const float* att   = (const float*)d_in[ia];
    const float* fea   = (const float*)d_in[ifea];
    const int*   label = (const int*)d_in[ilab];
    float* out = (float*)d_out;

    // Idempotent; safe under graph capture (no allocation, no sync).
    cudaFuncSetAttribute(main_kernel, cudaFuncAttributeMaxDynamicSharedMemorySize,
                         SMEM_MAIN);

    prep_kernel<<<NUSE, 128>>>(fea);
    pos_kernel<<<NB, 128>>>(att, fea, label);
    main_kernel<<<NCTA_A, 512, SMEM_MAIN>>>(att, 0);
    main_kernel<<<NCTA - NCTA_A, 512, SMEM_MAIN>>>(att, NCTA_A);
    reduce_kernel<<<NUSE, 256>>>();
    final_kernel<<<1, 128>>>(out);
}

// round 11
// speedup vs baseline: 1.0567x; 1.0507x over previous
#include <cuda_runtime.h>
#include <cuda_fp16.h>
#include <cstdint>
#include <math.h>

#define SN       150000
#define DIM      512
#define NB       100
#define NUSE     104                 // computed n columns (13 tiles of 8)
#define NTILES   13
#define TALF     0.07f
#define S_PER_CTA 512
#define NCTA     ((SN + S_PER_CTA - 1) / S_PER_CTA)   // 293
#define NCTA_A   (NCTA / 2)                           // 146

// B words: 32 ksteps x 104 n x 8 words (f16x2, fragment-packed)
#define BW        (32 * NUSE * 8)                     // 26624 words = 104 KB
#define AST_BYTES (16 * 3 * 2048)                     // 16 warps x 3 stages x 2KB fp32
#define SMEM_MAIN (BW * 4 + AST_BYTES + 16 * NUSE * 4)  // 211456 B

// Static device scratch (no allocations allowed)
__device__ __align__(1024) unsigned g_B[BW];
__device__ float g_Psum[NCTA * 128];
__device__ float g_pos[128];
__device__ float g_logZ[128];

// ---------------------------------------------------------------------------
__device__ __forceinline__ unsigned pack_f16x2(float lo, float hi) {
    unsigned r;  // first source -> high half
    asm("cvt.rn.f16x2.f32 %0, %1, %2;" : "=r"(r) : "f"(hi), "f"(lo));
    return r;
}
__device__ __forceinline__ void mma_f16acc(unsigned c[2], const unsigned* a,
                                           unsigned b0, unsigned b1) {
    asm volatile(
        "mma.sync.aligned.m16n8k16.row.col.f16.f16.f16.f16 "
        "{%0,%1},{%2,%3,%4,%5},{%6,%7},{%0,%1};\n"
        : "+r"(c[0]), "+r"(c[1])
        : "r"(a[0]), "r"(a[1]), "r"(a[2]), "r"(a[3]), "r"(b0), "r"(b1));
}
__device__ __forceinline__ void cp_async16(unsigned sdst, const void* gsrc) {
    asm volatile("cp.async.cg.shared.global [%0], [%1], 16;\n" :: "r"(sdst), "l"(gsrc));
}
__device__ __forceinline__ void cp_async16z(unsigned sdst, const void* gsrc, int sz) {
    asm volatile("cp.async.cg.shared.global [%0], [%1], 16, %2;\n"
                 :: "r"(sdst), "l"(gsrc), "r"(sz));
}
__device__ __forceinline__ unsigned smem_u32(const void* p) {
    return (unsigned)__cvta_generic_to_shared(p);
}

// ---------------------------------------------------------------------------
// prep: B'[n][k] = f16( fea[n][k] / (TAL*||fea[n]||) ), fragment layout:
//   word[(kstep*104 + n)*8 + c], kstep=k/16, c=2*tig+h -> k0 = kstep*16+h*8+2*tig
// ---------------------------------------------------------------------------
__global__ void prep_kernel(const float* __restrict__ fea) {
    int n = blockIdx.x;   // 0..103
    int t = threadIdx.x;  // 128
    __shared__ float red[128];
    __shared__ float row[512];
    float v[4]; float ss = 0.f;
    if (n < NB) {
#pragma unroll
        for (int i = 0; i < 4; i++) { v[i] = fea[n * DIM + t + i * 128]; ss += v[i] * v[i]; }
    } else { v[0] = v[1] = v[2] = v[3] = 0.f; }
    red[t] = ss; __syncthreads();
    for (int off = 64; off > 0; off >>= 1) { if (t < off) red[t] += red[t + off]; __syncthreads(); }
    float scale = (n < NB) ? (rsqrtf(red[0]) / TALF) : 0.f;
#pragma unroll
    for (int i = 0; i < 4; i++) row[t + i * 128] = v[i] * scale;
    __syncthreads();
#pragma unroll
    for (int i = 0; i < 2; i++) {
        int w = t + i * 128;
        int kstep = w >> 3;
        int c = w & 7;
        int k0 = kstep * 16 + (c & 1) * 8 + (c >> 1) * 2;
        g_B[(kstep * NUSE + n) * 8 + c] = pack_f16x2(row[k0], row[k0 + 1]);
    }
}

// ---------------------------------------------------------------------------
// pos: ex[label[n], n] exact fp32; label dtype sniffed (int64 vs int32)
// ---------------------------------------------------------------------------
__global__ void pos_kernel(const float* __restrict__ att,
                           const float* __restrict__ fea,
                           const int* __restrict__ label_raw) {
    int n = blockIdx.x, t = threadIdx.x;
    bool is64 = (label_raw[1] == 0) && (label_raw[3] == 0) &&
                (label_raw[5] == 0) && (label_raw[7] == 0);
    int lab = is64 ? (int)(((const long long*)label_raw)[n]) : label_raw[n];
    if (lab < 0) lab = 0;
    if (lab >= SN) lab = SN - 1;
    float dot = 0.f, asq = 0.f, fsq = 0.f;
    for (int d = t; d < DIM; d += 128) {
        float a = att[(size_t)d * SN + (size_t)lab];
        float f = fea[n * DIM + d];
        dot += a * f; asq += a * a; fsq += f * f;
    }
    __shared__ float r1[128], r2[128], r3[128];
    r1[t] = dot; r2[t] = asq; r3[t] = fsq; __syncthreads();
    for (int off = 64; off > 0; off >>= 1) {
        if (t < off) { r1[t] += r1[t+off]; r2[t] += r2[t+off]; r3[t] += r3[t+off]; }
        __syncthreads();
    }
    if (t == 0) g_pos[n] = r1[0] / (TALF * sqrtf(r2[0]) * sqrtf(r3[0]));
}

// ---------------------------------------------------------------------------
// main: 293 CTAs (2 launches) x 512 threads. Tile 512 s x 104 n, K=512.
//   A: deep cp.async pipeline (3 stages x 2KB fp32 per warp; 2 stages always
//   in flight -> high MLP -> DRAM saturation). Stage rows XOR-swizzled
//   (chunk ^= row&7) so the 16 compute LDS.32 per kstep are conflict-free.
//   B resident in smem. Pack->MMA->norms identical to the R8 math.
// ---------------------------------------------------------------------------
// issue one stage: 16 k-rows x 128B, thread covers row rr=lane>>1,
// chunks cb..cb+3 (cb=(lane&1)*4); zfill past SN.
#define ISSUE(q, buf)                                                       \
    do {                                                                    \
        const float* rowp_ = att + (size_t)((q) * 16 + rr) * SN_;           \
        unsigned db_ = AbaseS + (buf) * 2048 + rr * 128;                    \
        _Pragma("unroll")                                                   \
        for (int i_ = 0; i_ < 4; i_++) {                                    \
            cp_async16z(db_ + (unsigned)(((cb + i_) ^ (rr & 7)) * 16),      \
                        rowp_ + coff[i_], vld[i_]);                         \
        }                                                                   \
    } while (0)

#define COMMIT() asm volatile("cp.async.commit_group;\n" ::: "memory")

// per-kstep: read 16 A scalars from staged fp32 (conflict-free), accumulate
// exact norms, pack f16 fragments, run 26 MMAs against resident B.
#define COMPUTE(q, buf)                                                     \
    do {                                                                    \
        const char* ab_ = AwarpG + (buf) * 2048;                            \
        unsigned A_[2][4];                                                  \
        _Pragma("unroll")                                                   \
        for (int mf_ = 0; mf_ < 2; mf_++) {                                 \
            _Pragma("unroll")                                               \
            for (int jj_ = 0; jj_ < 2; jj_++) {                             \
                int j_ = 2 * mf_ + jj_;                                     \
                int c_ = 2 * j_ + g2;                                       \
                int sw0_ = ((c_ ^ r0) << 4) + u4;                           \
                int sw1_ = ((c_ ^ r1) << 4) + u4;                           \
                float a0_ = *(const float*)(ab_ + r0 * 128 + sw0_);         \
                float a1_ = *(const float*)(ab_ + r1 * 128 + sw1_);         \
                float a2_ = *(const float*)(ab_ + (r0 + 8) * 128 + sw0_);   \
                float a3_ = *(const float*)(ab_ + (r1 + 8) * 128 + sw1_);   \
                sq[j_] += a0_ * a0_ + a1_ * a1_ + a2_ * a2_ + a3_ * a3_;    \
                A_[mf_][jj_]     = pack_f16x2(a0_, a1_);                    \
                A_[mf_][jj_ + 2] = pack_f16x2(a2_, a3_);                    \
            }                                                               \
        }                                                                   \
        const uint2* bq_ = (const uint2*)Bsm + (q) * (NUSE * 4) + tig;      \
        _Pragma("unroll")                                                   \
        for (int nt_ = 0; nt_ < NTILES; nt_++) {                            \
            uint2 b_ = bq_[(nt_ * 8 + gid) * 4];                            \
            mma_f16acc(acc[0][nt_], A_[0], b_.x, b_.y);                     \
            mma_f16acc(acc[1][nt_], A_[1], b_.x, b_.y);                     \
        }                                                                   \
    } while (0)

__global__ void __launch_bounds__(512, 1)
main_kernel(const float* __restrict__ att, int cta_base) {
    extern __shared__ __align__(128) unsigned char smraw[];
    unsigned*      Bsm    = (unsigned*)smraw;                        // BW words
    unsigned char* Ast    = smraw + BW * 4;                          // A staging
    float*         colacc = (float*)(smraw + BW * 4 + AST_BYTES);    // 16 x NUSE

    const int tid   = threadIdx.x;
    const int lane  = tid & 31;
    const int warp  = tid >> 5;
    const int gid   = lane >> 2;
    const int tig   = lane & 3;
    const int cta   = cta_base + blockIdx.x;
    const int s_w   = cta * S_PER_CTA + warp * 32;
    const size_t SN_ = (size_t)SN;

    // cp.async geometry: row rr, chunks cb..cb+3 (16B each)
    const int rr = lane >> 1;
    const int cb = (lane & 1) * 4;
    int coff[4], vld[4];
#pragma unroll
    for (int i = 0; i < 4; i++) {
        int sref = s_w + (cb + i) * 4;
        int v = (SN - sref) * 4;
        vld[i]  = v < 0 ? 0 : (v > 16 ? 16 : v);
        coff[i] = (vld[i] > 0) ? (s_w + (cb + i) * 4) : 0;
    }

    // compute-read geometry
    const int g2 = gid >> 2;          // 0..1
    const int u4 = (gid & 3) * 4;     // byte offset within 16B chunk
    const int r0 = 2 * tig;           // k-row classes 2tig / 2tig+1 (+8)
    const int r1 = 2 * tig + 1;

    unsigned char* Awarp = Ast + warp * (3 * 2048);
    const unsigned AbaseS = smem_u32(Awarp);
    const char*    AwarpG = (const char*)Awarp;

    int  srow[4];
    bool pv[4];
#pragma unroll
    for (int j = 0; j < 4; j++) {
        srow[j] = s_w + 8 * j + gid;
        pv[j]   = (srow[j] < SN);
    }

    unsigned acc[2][NTILES][2];
#pragma unroll
    for (int a = 0; a < 2; a++)
#pragma unroll
        for (int b = 0; b < NTILES; b++) { acc[a][b][0] = 0u; acc[a][b][1] = 0u; }
    float sq[4] = {0.f, 0.f, 0.f, 0.f};

    // group 0: one-shot B fill (26624 words = 6656 x 16B, 13 per thread)
#pragma unroll
    for (int i = 0; i < 13; i++) {
        int w = (tid + i * 512) * 4;
        cp_async16(smem_u32(&Bsm[w]), &g_B[w]);
    }
    COMMIT();
    // groups 1..3: A stages 0..2
    ISSUE(0, 0); COMMIT();
    ISSUE(1, 1); COMMIT();
    ISSUE(2, 2); COMMIT();

    asm volatile("cp.async.wait_group 2;\n" ::: "memory");  // B + stage0 done
    __syncthreads();   // the ONLY CTA barrier before the epilogue

    // steady state: one group per iter (empty at tail), stage q guaranteed
    // ready by wait_group 2; 2 stages (4KB/warp) always in flight.
#pragma unroll 3
    for (int q = 0; q < 32; q++) {
        if (q > 0) {
            asm volatile("cp.async.wait_group 2;\n" ::: "memory");
            __syncwarp();
        }
        COMPUTE(q, q % 3);
        if (q + 3 < 32) ISSUE(q + 3, (q + 3) % 3);
        COMMIT();
    }

    // norm^2: quad-reduce over tig; every lane ends with the full row sum
#pragma unroll
    for (int j = 0; j < 4; j++) {
        sq[j] += __shfl_xor_sync(0xffffffffu, sq[j], 1);
        sq[j] += __shfl_xor_sync(0xffffffffu, sq[j], 2);
    }
    float inv[4];
#pragma unroll
    for (int j = 0; j < 4; j++) inv[j] = rsqrtf(sq[j]);

    // epilogue: unpack f16 accum, scale, exp, warp-level column sums
#pragma unroll
    for (int nt = 0; nt < NTILES; ++nt) {
        float e0 = 0.f, e1 = 0.f;
#pragma unroll
        for (int mf = 0; mf < 2; ++mf) {
            int j0 = 2 * mf, j1 = 2 * mf + 1;
            float2 v0 = __half22float2(*reinterpret_cast<__half2*>(&acc[mf][nt][0]));
            float2 v1 = __half22float2(*reinterpret_cast<__half2*>(&acc[mf][nt][1]));
            if (pv[j0]) {
                e0 += __expf(v0.x * inv[j0]);
                e1 += __expf(v0.y * inv[j0]);
            }
            if (pv[j1]) {
                e0 += __expf(v1.x * inv[j1]);
                e1 += __expf(v1.y * inv[j1]);
            }
        }
        e0 += __shfl_down_sync(0xffffffffu, e0, 16);
        e1 += __shfl_down_sync(0xffffffffu, e1, 16);
        e0 += __shfl_down_sync(0xffffffffu, e0, 8);
        e1 += __shfl_down_sync(0xffffffffu, e1, 8);
        e0 += __shfl_down_sync(0xffffffffu, e0, 4);
        e1 += __shfl_down_sync(0xffffffffu, e1, 4);
        if (gid == 0) {
            colacc[warp * NUSE + nt * 8 + 2 * tig]     = e0;
            colacc[warp * NUSE + nt * 8 + 2 * tig + 1] = e1;
        }
    }
    __syncthreads();

    if (tid < NUSE) {
        float t = 0.f;
#pragma unroll
        for (int g = 0; g < 16; ++g) t += colacc[g * NUSE + tid];
        g_Psum[cta * 128 + tid] = t;
    }
}

// ---------------------------------------------------------------------------
__global__ void reduce_kernel() {
    int n = blockIdx.x;    // 0..NUSE-1
    int t = threadIdx.x;   // 256
    __shared__ float red[256];
    float sum = 0.f;
    for (int c = t; c < NCTA; c += 256) sum += g_Psum[c * 128 + n];
    red[t] = sum; __syncthreads();
    for (int off = 128; off > 0; off >>= 1) { if (t < off) red[t] += red[t + off]; __syncthreads(); }
    if (t == 0) g_logZ[n] = logf(red[0]);
}

__global__ void final_kernel(float* __restrict__ out) {
    int t = threadIdx.x;   // 128
    __shared__ float red[128];
    float v = (t < NB) ? (g_logZ[t] - g_pos[t]) : 0.f;
    red[t] = v; __syncthreads();
    for (int off = 64; off > 0; off >>= 1) { if (t < off) red[t] += red[t + off]; __syncthreads(); }
    if (t == 0) out[0] = red[0] / (float)NB;
}

// ---------------------------------------------------------------------------
extern "C" void kernel_launch(void* const* d_in, const int* in_sizes, int n_in,
                              void* d_out, int out_size) {
    int ia = 0, ifea = 1, ilab = 2;
    for (int i = 0; i < n_in; i++) {
        if (in_sizes[i] > 10000000) ia = i;
        else if (in_sizes[i] > 100000) ifea = i;
        else ilab = i;
    }
    const float* att   = (const float*)d_in[ia];
    const float* fea   = (const float*)d_in[ifea];
    const int*   label = (const int*)d_in[ilab];
    float* out = (float*)d_out;

    // Idempotent; safe under graph capture (no allocation, no sync).
    cudaFuncSetAttribute(main_kernel, cudaFuncAttributeMaxDynamicSharedMemorySize,
                         SMEM_MAIN);

    prep_kernel<<<NUSE, 128>>>(fea);
    pos_kernel<<<NB, 128>>>(att, fea, label);
    main_kernel<<<NCTA_A, 512, SMEM_MAIN>>>(att, 0);
    main_kernel<<<NCTA - NCTA_A, 512, SMEM_MAIN>>>(att, NCTA_A);
    reduce_kernel<<<NUSE, 256>>>();
    final_kernel<<<1, 128>>>(out);
}